// round 15
// baseline (speedup 1.0000x reference)
#include <cuda_runtime.h>
#include <cuda_bf16.h>
#include <cstdint>

#define NB 256          // cells in minibatch
#define NG 2000         // genes_oi
#define NL 64           // latent dim
#define NC 128          // spline bins
#define NCUTS_C 500000
#define LOG_NBINS 4.852030263919617f   // ln(128)
#define LOG2E 1.4426950408889634f
#define LN2 0.6931471805599453f
#define NBUCKET (NG * 4)               // (gene, quarter) buckets
#define CAP 160                        // bucket capacity (mean 62.5, max ~97)

#define LAT_BLOCKS 8
#define WT_BLOCKS NG                   // weight transpose blocks
#define CUT_PAIRS (NCUTS_C / 2)
#define CUT_BLOCKS ((CUT_PAIRS + 255) / 256)
#define PREP_SMEM (64 * 129 * 4)       // f32 [64][129] transpose staging

#define NBLK 444                       // persistent gemm blocks (3/SM x 148)
#define NSLOT 111                      // NBLK / 4 quarters
#define LDA 72                         // Asm row stride, bf16
#define LDB 72                         // Bt row stride, bf16 (64 data + 8 pad)
#define LDH 136                        // hsm row stride, bf16

// gemm smem layout (bytes) — all 16B aligned
#define OFF_ASM 0
#define SZ_ASM   (64 * LDA * 2)                 // 9216
#define OFF_BT0  (OFF_ASM + SZ_ASM)
#define SZ_BTBUF (128 * LDB * 2)                // 18432
#define OFF_HSM  (OFF_BT0 + 2 * SZ_BTBUF)       // 46080
#define SZ_HSM   (64 * LDH * 2)                 // 17408
#define OFF_HTS0 (OFF_HSM + SZ_HSM)             // 63488 (2 x 512)
#define OFF_RW0  (OFF_HTS0 + 1024)              // 64512 (2 x 256)
#define OFF_RECS0 (OFF_RW0 + 512)               // 65024 (2 x 320)
#define OFF_CNT0  (OFF_RECS0 + 640)             // 65664 (2 x 256)
#define OFF_HIST0 (OFF_CNT0 + 512)              // 66176 (2 x 16)
#define OFF_LSB   (OFF_HIST0 + 32)              // 66208 (64 x 4 x 4)
#define OFF_LSE   (OFF_LSB + 1024)              // 67232 (64 x 4)
#define SMEM_TOTAL (OFF_LSE + 256)              // 67488

// ---- static device scratch (allocation-free rule) ----
// INVARIANT: mutable state zero at start of every launch (module-load zero
// + restore-to-zero in gemm_kernel after each single read).
__device__ __nv_bfloat16 g_lat[NB * NL];
__device__ __nv_bfloat16 g_wt[(size_t)NG * NC * NL];  // [g][c][k] bf16 (x log2e)
__device__ int g_counts[NG * NB];              // fragment counts, [g][b]
__device__ int g_hist[NBUCKET];
__device__ unsigned short g_recs[NBUCKET * CAP];
__device__ double g_acc;
__device__ unsigned int g_done;

__device__ __forceinline__ void cpasync16(uint32_t dst, const void* src) {
    asm volatile("cp.async.ca.shared.global [%0], [%1], 16;\n"
                 :: "r"(dst), "l"(src));
}
__device__ __forceinline__ void cpasync4(uint32_t dst, const void* src) {
    asm volatile("cp.async.ca.shared.global [%0], [%1], 4;\n"
                 :: "r"(dst), "l"(src));
}
__device__ __forceinline__ void ldsm_x4(uint32_t &r0, uint32_t &r1,
                                        uint32_t &r2, uint32_t &r3, uint32_t addr) {
    asm volatile("ldmatrix.sync.aligned.m8n8.x4.shared.b16 {%0,%1,%2,%3}, [%4];"
                 : "=r"(r0), "=r"(r1), "=r"(r2), "=r"(r3) : "r"(addr));
}
__device__ __forceinline__ float ex2f(float x) {
    float r;
    asm("ex2.approx.ftz.f32 %0, %1;" : "=f"(r) : "f"(x));
    return r;
}
__device__ __forceinline__ float lg2f(float x) {
    float r;
    asm("lg2.approx.ftz.f32 %0, %1;" : "=f"(r) : "f"(x));
    return r;
}

// ============================================================
// Kernel 1: fused prep.
//  blocks [0,8): latent -> bf16
//  blocks [8, 8+NG): weight gather + (f32 * log2e) -> bf16 + transpose
//  rest: cut prep (2 cuts/thread): fragment bincount + bucket scatter
// ============================================================
__device__ __forceinline__ void cut_one(int lix, int cxg, float coord) {
    const int lb = lix / NG;
    const int lg = lix - lb * NG;
    atomicAdd(&g_counts[lg * NB + lb], 1);

    const int b = cxg / NG;
    const int g = cxg - b * NG;
    int bin = (int)(coord * 128.0f);
    bin = max(0, min(127, bin));
    const int bucket = g * 4 + (b >> 6);
    const int pos = atomicAdd(&g_hist[bucket], 1);
    if (pos < CAP)
        g_recs[bucket * CAP + pos] = (unsigned short)(((b & 63) << 7) | bin);
}

__global__ __launch_bounds__(256) void prep_kernel(
    const int* __restrict__ local_ix,
    const int* __restrict__ cxg_ix,
    const float* __restrict__ coords,
    const float* __restrict__ latent,
    const int* __restrict__ genes_oi,
    const float* __restrict__ logit_weight)
{
    const int tid = threadIdx.x;
    if (blockIdx.x < LAT_BLOCKS) {
        #pragma unroll
        for (int j = 0; j < 8; j++) {
            int idx = blockIdx.x * 2048 + j * 256 + tid;
            g_lat[idx] = __float2bfloat16(latent[idx]);
        }
        return;
    }
    if (blockIdx.x < LAT_BLOCKS + WT_BLOCKS) {
        extern __shared__ float ws[];        // [64][129]
        const int g = blockIdx.x - LAT_BLOCKS;
        const int gg = genes_oi[g];
        const float4* src = (const float4*)(logit_weight + (size_t)gg * (NL * NC));
        #pragma unroll
        for (int i = 0; i < 8; i++) {
            int idx = tid + i * 256;          // 2048 float4
            int k = idx >> 5, c4 = (idx & 31) * 4;
            float4 v = src[idx];
            ws[k * 129 + c4 + 0] = v.x;
            ws[k * 129 + c4 + 1] = v.y;
            ws[k * 129 + c4 + 2] = v.z;
            ws[k * 129 + c4 + 3] = v.w;
        }
        __syncthreads();
        __nv_bfloat162* dstw = (__nv_bfloat162*)(g_wt + (size_t)g * (NC * NL));
        #pragma unroll
        for (int i = 0; i < 16; i++) {
            int idx = tid + i * 256;          // 4096 bf162
            int c = idx >> 5, kp = idx & 31;
            float lo = ws[(2 * kp) * 129 + c] * LOG2E;
            float hi = ws[(2 * kp + 1) * 129 + c] * LOG2E;
            dstw[idx] = __float22bfloat162_rn(make_float2(lo, hi));
        }
        return;
    }
    const int base = (blockIdx.x - LAT_BLOCKS - WT_BLOCKS) * 256 + tid;
    if (base < CUT_PAIRS) {
        const int2 lix = ((const int2*)local_ix)[base];
        const int2 cxg = ((const int2*)cxg_ix)[base];
        const float2 co = ((const float2*)coords)[base];
        cut_one(lix.x, cxg.x, co.x);
        cut_one(lix.y, cxg.y, co.y);
    }
}

// ============================================================
// Kernel 2: persistent quarter-gene GEMM pipeline (base-2 logits).
// 444 blocks (3/SM); block = (quarter = bx&3, slot = bx>>2);
// genes g = slot + 111*it. Tile 64 cells x 128 bins, acc 32 regs.
// cp.async double-buffers weights + heights + rho + cut recs + counts
// + hist one gene ahead. Merged epilogue; LSE || Poisson; cuts from smem.
// ============================================================
__global__ __launch_bounds__(256, 3) void gemm_kernel(
    const int* __restrict__ genes_oi,
    const float* __restrict__ spline_heights,
    const int* __restrict__ cells_oi,
    const float* __restrict__ rho_weight,
    const float* __restrict__ rho_bias,
    const int* __restrict__ libsize,
    float* __restrict__ out)
{
    extern __shared__ char smem_raw[];
    const uint32_t smem_u = (uint32_t)__cvta_generic_to_shared(smem_raw);
    __nv_bfloat16* Asm = (__nv_bfloat16*)(smem_raw + OFF_ASM);
    __nv_bfloat16* hsm = (__nv_bfloat16*)(smem_raw + OFF_HSM);
    float* lsebuf = (float*)(smem_raw + OFF_LSB);
    float* lse_sh = (float*)(smem_raw + OFF_LSE);

    const int tid = threadIdx.x;
    const int quarter = blockIdx.x & 3;
    const int slot = blockIdx.x >> 2;
    const int ngenes = (slot < 2) ? 19 : 18;    // 2*19 + 109*18 = 2000

    // --- load this quarter's 64 latent rows once ---
    const uint32_t* latw = (const uint32_t*)g_lat + quarter * 2048;
    uint32_t* asw = (uint32_t*)Asm;
    #pragma unroll
    for (int it = 0; it < 8; it++) {
        int i = tid + it * 256;            // 2048 words
        int b = i >> 5, w = i & 31;
        asw[b * (LDA / 2) + w] = latw[i];
    }

    const int warp = tid >> 5, lane = tid & 31;
    const int mw = warp >> 2, nw = warp & 3;
    const int grp = lane >> 2, tig = lane & 3;

    // ldmatrix lane addresses
    const int rA = (lane & 7) + ((lane >> 3) & 1) * 8;
    const int kA = (lane >> 4) * 8;
    const uint32_t aAddr = smem_u + OFF_ASM
                         + (uint32_t)(((mw * 32 + rA) * LDA + kA) * 2);
    const int rB = (lane & 7) + (lane >> 4) * 8;
    const int kB = ((lane >> 3) & 1) * 8;
    const uint32_t bOff = (uint32_t)(((nw * 32 + rB) * LDB + kB) * 2);

    // --- prefetch helper (gene gn into buffer pb) ---
    auto prefetch = [&](int gidx, int gg, int pb) {
        const char* wsrc = (const char*)(g_wt + (size_t)gidx * (NC * NL));
        uint32_t bt = smem_u + OFF_BT0 + pb * SZ_BTBUF;
        #pragma unroll
        for (int j = 0; j < 4; j++) {
            int idx = tid + j * 256, c = idx >> 3, ch = idx & 7;
            cpasync16(bt + c * 144 + ch * 16, wsrc + c * 128 + ch * 16);
        }
        const int t = gidx * 4 + quarter;
        if (tid < 32)
            cpasync16(smem_u + OFF_HTS0 + pb * 512 + tid * 16,
                      (const char*)(spline_heights + (size_t)gg * NC) + tid * 16);
        else if (tid < 48)
            cpasync16(smem_u + OFF_RW0 + pb * 256 + (tid - 32) * 16,
                      (const char*)(rho_weight + (size_t)gg * NL) + (tid - 32) * 16);
        else if (tid < 68)
            cpasync16(smem_u + OFF_RECS0 + pb * 320 + (tid - 48) * 16,
                      (const char*)(g_recs + (size_t)t * CAP) + (tid - 48) * 16);
        else if (tid < 84)
            cpasync16(smem_u + OFF_CNT0 + pb * 256 + (tid - 68) * 16,
                      (const char*)(g_counts + gidx * NB + quarter * 64) + (tid - 68) * 16);
        else if (tid == 84)
            cpasync4(smem_u + OFF_HIST0 + pb * 16, (const char*)(g_hist + t));
    };

    // --- prologue prefetch: gene 0 into buf 0 ---
    int gg_next = genes_oi[slot];
    prefetch(slot, gg_next, 0);
    asm volatile("cp.async.commit_group;\n");

    float acc = 0.0f;
    int gg_cur;

    for (int it = 0; it < ngenes; it++) {
        const int g = slot + NSLOT * it;
        const int buf = it & 1;
        gg_cur = gg_next;

        if (it + 1 < ngenes) {
            const int gn = slot + NSLOT * (it + 1);
            gg_next = genes_oi[gn];
            prefetch(gn, gg_next, buf ^ 1);
            asm volatile("cp.async.commit_group;\n");
            asm volatile("cp.async.wait_group 1;\n");
        } else {
            asm volatile("cp.async.wait_group 0;\n");
        }
        __syncthreads();     // buffers ready; also orders prev-gene hsm reads

        const uint32_t btBase = smem_u + OFF_BT0 + buf * SZ_BTBUF;
        const float* hts = (const float*)(smem_raw + OFF_HTS0 + buf * 512);
        const float* rw_sh = (const float*)(smem_raw + OFF_RW0 + buf * 256);
        const unsigned short* recs_sh =
            (const unsigned short*)(smem_raw + OFF_RECS0 + buf * 320);
        const int* cnt_sh = (const int*)(smem_raw + OFF_CNT0 + buf * 256);
        const int ncuts = min(*(const int*)(smem_raw + OFF_HIST0 + buf * 16), CAP);
        const int t = g * 4 + quarter;

        // --- MMA phase (ldmatrix fragment loads) ---
        float c[2][4][4];
        #pragma unroll
        for (int mi = 0; mi < 2; mi++)
            #pragma unroll
            for (int nj = 0; nj < 4; nj++)
                #pragma unroll
                for (int q = 0; q < 4; q++) c[mi][nj][q] = 0.0f;

        #pragma unroll
        for (int ki = 0; ki < 4; ki++) {
            uint32_t a[2][4];
            #pragma unroll
            for (int mi = 0; mi < 2; mi++)
                ldsm_x4(a[mi][0], a[mi][1], a[mi][2], a[mi][3],
                        aAddr + mi * (16 * LDA * 2) + ki * 32);
            uint32_t b[4][2];
            #pragma unroll
            for (int p = 0; p < 2; p++)
                ldsm_x4(b[2 * p][0], b[2 * p][1], b[2 * p + 1][0], b[2 * p + 1][1],
                        btBase + bOff + p * (16 * LDB * 2) + ki * 32);
            #pragma unroll
            for (int mi = 0; mi < 2; mi++)
                #pragma unroll
                for (int nj = 0; nj < 4; nj++) {
                    asm volatile(
                        "mma.sync.aligned.m16n8k16.row.col.f32.bf16.bf16.f32 "
                        "{%0,%1,%2,%3}, {%4,%5,%6,%7}, {%8,%9}, {%0,%1,%2,%3};"
                        : "+f"(c[mi][nj][0]), "+f"(c[mi][nj][1]),
                          "+f"(c[mi][nj][2]), "+f"(c[mi][nj][3])
                        : "r"(a[mi][0]), "r"(a[mi][1]), "r"(a[mi][2]), "r"(a[mi][3]),
                          "r"(b[nj][0]), "r"(b[nj][1]));
                }
        }

        // --- Merged epilogue (base-2): h' = c + hts*log2e; store h'; ex2 sums ---
        float2 ht[4];
        #pragma unroll
        for (int nj = 0; nj < 4; nj++) {
            float2 v = *(const float2*)(hts + nw * 32 + 8 * nj + 2 * tig);
            ht[nj] = make_float2(v.x * LOG2E, v.y * LOG2E);
        }

        #pragma unroll
        for (int mi = 0; mi < 2; mi++) {
            const int r0 = mw * 32 + 16 * mi + grp;
            float s0 = 0.0f, s1 = 0.0f;
            #pragma unroll
            for (int nj = 0; nj < 4; nj++) {
                const int col = nw * 32 + 8 * nj + 2 * tig;
                const float h00 = c[mi][nj][0] + ht[nj].x;
                const float h01 = c[mi][nj][1] + ht[nj].y;
                const float h10 = c[mi][nj][2] + ht[nj].x;
                const float h11 = c[mi][nj][3] + ht[nj].y;
                *(__nv_bfloat162*)(hsm + r0 * LDH + col) =
                    __float22bfloat162_rn(make_float2(h00, h01));
                *(__nv_bfloat162*)(hsm + (r0 + 8) * LDH + col) =
                    __float22bfloat162_rn(make_float2(h10, h11));
                s0 += ex2f(h00) + ex2f(h01);
                s1 += ex2f(h10) + ex2f(h11);
            }
            s0 += __shfl_xor_sync(0xffffffffu, s0, 1);
            s0 += __shfl_xor_sync(0xffffffffu, s0, 2);
            s1 += __shfl_xor_sync(0xffffffffu, s1, 1);
            s1 += __shfl_xor_sync(0xffffffffu, s1, 2);
            if (tig == 0) {
                lsebuf[r0 * 4 + nw] = s0;
                lsebuf[(r0 + 8) * 4 + nw] = s1;
            }
        }
        __syncthreads();

        // --- lg2 finalize (tids 0..63) || Poisson (tids 128..191) ---
        if (tid < 64) {
            float tt = lsebuf[tid * 4 + 0] + lsebuf[tid * 4 + 1]
                     + lsebuf[tid * 4 + 2] + lsebuf[tid * 4 + 3];
            lse_sh[tid] = lg2f(tt);
        } else if (tid >= 128 && tid < 192) {
            const int r = tid - 128;
            const uint4* ar = (const uint4*)(Asm + r * LDA);
            float rd = 0.0f;
            #pragma unroll
            for (int j = 0; j < 8; j++) {
                uint4 w = ar[j];
                float2 v0 = __bfloat1622float2(*reinterpret_cast<const __nv_bfloat162*>(&w.x));
                float2 v1 = __bfloat1622float2(*reinterpret_cast<const __nv_bfloat162*>(&w.y));
                float2 v2 = __bfloat1622float2(*reinterpret_cast<const __nv_bfloat162*>(&w.z));
                float2 v3 = __bfloat1622float2(*reinterpret_cast<const __nv_bfloat162*>(&w.w));
                rd += v0.x * rw_sh[8 * j + 0] + v0.y * rw_sh[8 * j + 1]
                    + v1.x * rw_sh[8 * j + 2] + v1.y * rw_sh[8 * j + 3]
                    + v2.x * rw_sh[8 * j + 4] + v2.y * rw_sh[8 * j + 5]
                    + v3.x * rw_sh[8 * j + 6] + v3.y * rw_sh[8 * j + 7];
            }
            const int b_glob = quarter * 64 + r;
            const float rate = rho_bias[gg_cur] * __expf(rd)
                             * (float)libsize[cells_oi[b_glob]];
            const int cnt = cnt_sh[r];
            g_counts[g * NB + b_glob] = 0;          // restore invariant
            float lg = 0.0f;
            for (int k = 2; k <= cnt; k++) lg += __logf((float)k);
            acc += (float)cnt * __logf(rate) - rate - lg;
        }
        __syncthreads();    // hsm + lse_sh ready for cut lookups

        // --- cut likelihood from smem recs: (h' - lse2) * ln2 ---
        {
            for (int j = tid; j < ncuts; j += 256) {
                const unsigned int rec = recs_sh[j];
                const int b_loc = rec >> 7;
                acc += (__bfloat162float(hsm[b_loc * LDH + (rec & 127)])
                        - lse_sh[b_loc]) * LN2;
            }
            if (tid == 0) {
                acc += (float)ncuts * LOG_NBINS;
                g_hist[t] = 0;                      // restore invariant
            }
        }
        // next iteration's top __syncthreads orders hsm/lse_sh reuse
    }

    // --- block reduce + global accumulate + ticketed finalization ---
    {
        __shared__ float sred[8];
        #pragma unroll
        for (int o = 16; o > 0; o >>= 1)
            acc += __shfl_xor_sync(0xffffffffu, acc, o);
        if (lane == 0) sred[warp] = acc;
        __syncthreads();
        if (tid == 0) {
            float tt = 0.0f;
            #pragma unroll
            for (int w = 0; w < 8; w++) tt += sred[w];
            atomicAdd(&g_acc, (double)tt);
            __threadfence();
            unsigned int v = atomicAdd(&g_done, 1u);
            if (v == gridDim.x - 1) {
                __threadfence();
                double a = *((volatile double*)&g_acc);
                out[0] = (float)(-a);
                g_acc = 0.0;
                g_done = 0u;
            }
        }
    }
}

extern "C" void kernel_launch(void* const* d_in, const int* in_sizes, int n_in,
                              void* d_out, int out_size) {
    const float* latent     = (const float*)d_in[0];
    const int*   genes_oi   = (const int*)d_in[1];
    const int*   cells_oi   = (const int*)d_in[2];
    const float* coords     = (const float*)d_in[3];
    const int*   cut_cxg    = (const int*)d_in[4];
    const int*   local_cxg  = (const int*)d_in[6];
    const float* logit_w    = (const float*)d_in[7];
    const float* rho_w      = (const float*)d_in[8];
    const float* rho_b      = (const float*)d_in[9];
    const int*   libsize    = (const int*)d_in[10];
    const float* spline_h   = (const float*)d_in[11];
    float* out = (float*)d_out;

    cudaFuncSetAttribute(gemm_kernel,
                         cudaFuncAttributeMaxDynamicSharedMemorySize, SMEM_TOTAL);

    prep_kernel<<<LAT_BLOCKS + WT_BLOCKS + CUT_BLOCKS, 256, PREP_SMEM>>>(
        local_cxg, cut_cxg, coords, latent, genes_oi, logit_w);
    gemm_kernel<<<NBLK, 256, SMEM_TOTAL>>>(genes_oi, spline_h, cells_oi,
                                           rho_w, rho_b, libsize, out);
}

// round 16
// speedup vs baseline: 1.0678x; 1.0678x over previous
#include <cuda_runtime.h>
#include <cuda_bf16.h>
#include <cstdint>

#define NB 256          // cells in minibatch
#define NG 2000         // genes_oi
#define NL 64           // latent dim
#define NC 128          // spline bins
#define NCUTS_C 500000
#define LOG_NBINS 4.852030263919617f   // ln(128)
#define LOG2E 1.4426950408889634f
#define LN2 0.6931471805599453f
#define NBUCKET (NG * 2)               // (gene, half) buckets
#define CAP 320                        // fixed bucket capacity (mean 125, max ~172)

#define LAT_BLOCKS 8
#define WT_BLOCKS NG                   // weight transpose blocks
#define CUT_PAIRS (NCUTS_C / 2)
#define CUT_BLOCKS ((CUT_PAIRS + 255) / 256)
#define PREP_SMEM (64 * 129 * 4)       // f32 [64][129] transpose staging

#define NBLK 296                       // persistent gemm blocks (2/SM x 148)
#define LDA 72                         // Asm row stride, bf16
#define LDB 72                         // Bt row stride, bf16 (64 data + 8 pad)
#define LDH 136                        // hsm row stride, bf16

// gemm smem layout (bytes)
#define OFF_ASM 0
#define SZ_ASM  (128 * LDA * 2)                 // 18432
#define SZ_BTBUF (128 * LDB * 2)                // 18432
#define OFF_BT0 (OFF_ASM + SZ_ASM)
#define OFF_HSM (OFF_BT0 + 2 * SZ_BTBUF)        // 55296
#define SZ_HSM  (128 * LDH * 2)                 // 34816
#define OFF_HTS0 (OFF_HSM + SZ_HSM)             // 90112 (2 x 512)
#define OFF_RW0  (OFF_HTS0 + 1024)              // 91136 (2 x 256)
#define OFF_LSB  (OFF_RW0 + 512)                // 91648
#define OFF_LSE  (OFF_LSB + 2048)               // 93696
#define OFF_RECS0 (OFF_LSE + 512)               // 94208 (2 x 640)
#define OFF_CNT0  (OFF_RECS0 + 1280)            // 95488 (2 x 512)
#define OFF_HIST0 (OFF_CNT0 + 1024)             // 96512 (2 x 16)
#define SMEM_TOTAL (OFF_HIST0 + 32)             // 96544

// ---- static device scratch (allocation-free rule) ----
// INVARIANT: mutable state zero at start of every launch (module-load zero
// + restore-to-zero in gemm_kernel after each single read).
__device__ __nv_bfloat16 g_lat[NB * NL];
__device__ __nv_bfloat16 g_wt[(size_t)NG * NC * NL];  // [g][c][k] bf16 (x log2e)
__device__ int g_counts[NG * NB];              // fragment counts, [g][b]
__device__ int g_hist[NBUCKET];
__device__ unsigned short g_recs[NBUCKET * CAP];
__device__ double g_acc;
__device__ unsigned int g_done;

__device__ __forceinline__ void cpasync16(uint32_t dst, const void* src) {
    asm volatile("cp.async.ca.shared.global [%0], [%1], 16;\n"
                 :: "r"(dst), "l"(src));
}
__device__ __forceinline__ void cpasync4(uint32_t dst, const void* src) {
    asm volatile("cp.async.ca.shared.global [%0], [%1], 4;\n"
                 :: "r"(dst), "l"(src));
}
__device__ __forceinline__ void ldsm_x4(uint32_t &r0, uint32_t &r1,
                                        uint32_t &r2, uint32_t &r3, uint32_t addr) {
    asm volatile("ldmatrix.sync.aligned.m8n8.x4.shared.b16 {%0,%1,%2,%3}, [%4];"
                 : "=r"(r0), "=r"(r1), "=r"(r2), "=r"(r3) : "r"(addr));
}
__device__ __forceinline__ float ex2f(float x) {
    float r;
    asm("ex2.approx.ftz.f32 %0, %1;" : "=f"(r) : "f"(x));
    return r;
}
__device__ __forceinline__ float lg2f(float x) {
    float r;
    asm("lg2.approx.ftz.f32 %0, %1;" : "=f"(r) : "f"(x));
    return r;
}

// ============================================================
// Kernel 1: fused prep.
//  blocks [0,8): latent -> bf16
//  blocks [8, 8+NG): weight gather + (f32 * log2e) -> bf16 + transpose
//  rest: cut prep (2 cuts/thread): fragment bincount + bucket scatter
// ============================================================
__device__ __forceinline__ void cut_one(int lix, int cxg, float coord) {
    const int lb = lix / NG;
    const int lg = lix - lb * NG;
    atomicAdd(&g_counts[lg * NB + lb], 1);

    const int b = cxg / NG;
    const int g = cxg - b * NG;
    int bin = (int)(coord * 128.0f);
    bin = max(0, min(127, bin));
    const int bucket = g * 2 + (b >> 7);
    const int pos = atomicAdd(&g_hist[bucket], 1);
    if (pos < CAP)
        g_recs[bucket * CAP + pos] = (unsigned short)(((b & 127) << 7) | bin);
}

__global__ __launch_bounds__(256) void prep_kernel(
    const int* __restrict__ local_ix,
    const int* __restrict__ cxg_ix,
    const float* __restrict__ coords,
    const float* __restrict__ latent,
    const int* __restrict__ genes_oi,
    const float* __restrict__ logit_weight)
{
    const int tid = threadIdx.x;
    if (blockIdx.x < LAT_BLOCKS) {
        #pragma unroll
        for (int j = 0; j < 8; j++) {
            int idx = blockIdx.x * 2048 + j * 256 + tid;
            g_lat[idx] = __float2bfloat16(latent[idx]);
        }
        return;
    }
    if (blockIdx.x < LAT_BLOCKS + WT_BLOCKS) {
        extern __shared__ float ws[];        // [64][129]
        const int g = blockIdx.x - LAT_BLOCKS;
        const int gg = genes_oi[g];
        const float4* src = (const float4*)(logit_weight + (size_t)gg * (NL * NC));
        #pragma unroll
        for (int i = 0; i < 8; i++) {
            int idx = tid + i * 256;          // 2048 float4
            int k = idx >> 5, c4 = (idx & 31) * 4;
            float4 v = src[idx];
            ws[k * 129 + c4 + 0] = v.x;
            ws[k * 129 + c4 + 1] = v.y;
            ws[k * 129 + c4 + 2] = v.z;
            ws[k * 129 + c4 + 3] = v.w;
        }
        __syncthreads();
        __nv_bfloat162* dstw = (__nv_bfloat162*)(g_wt + (size_t)g * (NC * NL));
        #pragma unroll
        for (int i = 0; i < 16; i++) {
            int idx = tid + i * 256;          // 4096 bf162
            int c = idx >> 5, kp = idx & 31;
            float lo = ws[(2 * kp) * 129 + c] * LOG2E;
            float hi = ws[(2 * kp + 1) * 129 + c] * LOG2E;
            dstw[idx] = __float22bfloat162_rn(make_float2(lo, hi));
        }
        return;
    }
    const int base = (blockIdx.x - LAT_BLOCKS - WT_BLOCKS) * 256 + tid;
    if (base < CUT_PAIRS) {
        const int2 lix = ((const int2*)local_ix)[base];
        const int2 cxg = ((const int2*)cxg_ix)[base];
        const float2 co = ((const float2*)coords)[base];
        cut_one(lix.x, cxg.x, co.x);
        cut_one(lix.y, cxg.y, co.y);
    }
}

// ============================================================
// Kernel 2: persistent half-gene GEMM pipeline (base-2 logits).
// 296 blocks (2/SM); block = (half, slot); genes g = slot + 148*it.
// ldmatrix fragment loads; cp.async double-buffers weights + heights +
// rho + cut recs + counts + hist one gene ahead. Merged epilogue
// (h' store + ex2 partials); Poisson || lg2 finalize; cuts from smem;
// ticketed finalization + restore-to-zero.
// ============================================================
__global__ __launch_bounds__(256, 2) void gemm_kernel(
    const int* __restrict__ genes_oi,
    const float* __restrict__ spline_heights,
    const int* __restrict__ cells_oi,
    const float* __restrict__ rho_weight,
    const float* __restrict__ rho_bias,
    const int* __restrict__ libsize,
    float* __restrict__ out)
{
    extern __shared__ char smem_raw[];
    const uint32_t smem_u = (uint32_t)__cvta_generic_to_shared(smem_raw);
    __nv_bfloat16* Asm = (__nv_bfloat16*)(smem_raw + OFF_ASM);
    __nv_bfloat16* hsm = (__nv_bfloat16*)(smem_raw + OFF_HSM);
    float* lsebuf = (float*)(smem_raw + OFF_LSB);
    float* lse_sh = (float*)(smem_raw + OFF_LSE);

    const int tid = threadIdx.x;
    const int half = blockIdx.x & 1;
    const int slot = blockIdx.x >> 1;
    const int ngenes = (slot < 76) ? 14 : 13;   // 76*14 + 72*13 = 2000

    // --- load this half's 128 latent rows once ---
    const uint32_t* latw = (const uint32_t*)g_lat + half * 4096;
    uint32_t* asw = (uint32_t*)Asm;
    #pragma unroll
    for (int it = 0; it < 16; it++) {
        int i = tid + it * 256;
        int b = i >> 5, w = i & 31;
        asw[b * (LDA / 2) + w] = latw[i];
    }

    const int warp = tid >> 5, lane = tid & 31;
    const int mw = warp >> 2, nw = warp & 3;
    const int grp = lane >> 2, tig = lane & 3;

    // ldmatrix lane addresses (A: x4 tiles; B: x4 = nj pair)
    const int rA = (lane & 7) + ((lane >> 3) & 1) * 8;
    const int kA = (lane >> 4) * 8;
    const uint32_t aAddr = smem_u + OFF_ASM
                         + (uint32_t)(((mw * 64 + rA) * LDA + kA) * 2);
    const int rB = (lane & 7) + (lane >> 4) * 8;
    const int kB = ((lane >> 3) & 1) * 8;
    const uint32_t bOff = (uint32_t)(((nw * 32 + rB) * LDB + kB) * 2);

    // --- prefetch helper: gene gidx (global id gg) into buffer pb ---
    auto prefetch = [&](int gidx, int gg, int pb) {
        const char* wsrc = (const char*)(g_wt + (size_t)gidx * (NC * NL));
        uint32_t bt = smem_u + OFF_BT0 + pb * SZ_BTBUF;
        #pragma unroll
        for (int j = 0; j < 4; j++) {
            int idx = tid + j * 256, c = idx >> 3, ch = idx & 7;
            cpasync16(bt + c * 144 + ch * 16, wsrc + c * 128 + ch * 16);
        }
        const int t = gidx * 2 + half;
        if (tid < 32)
            cpasync16(smem_u + OFF_HTS0 + pb * 512 + tid * 16,
                      (const char*)(spline_heights + (size_t)gg * NC) + tid * 16);
        else if (tid < 48)
            cpasync16(smem_u + OFF_RW0 + pb * 256 + (tid - 32) * 16,
                      (const char*)(rho_weight + (size_t)gg * NL) + (tid - 32) * 16);
        else if (tid < 88)      // 40 x 16B = 640B = CAP recs
            cpasync16(smem_u + OFF_RECS0 + pb * 640 + (tid - 48) * 16,
                      (const char*)(g_recs + (size_t)t * CAP) + (tid - 48) * 16);
        else if (tid < 120)     // 32 x 16B = 512B = 128 counts
            cpasync16(smem_u + OFF_CNT0 + pb * 512 + (tid - 88) * 16,
                      (const char*)(g_counts + gidx * NB + half * 128) + (tid - 88) * 16);
        else if (tid == 120)
            cpasync4(smem_u + OFF_HIST0 + pb * 16, (const char*)(g_hist + t));
    };

    // --- prologue prefetch: gene 0 into buf 0 ---
    int gg_next = genes_oi[slot];
    prefetch(slot, gg_next, 0);
    asm volatile("cp.async.commit_group;\n");

    float acc = 0.0f;
    int gg_cur;

    for (int it = 0; it < ngenes; it++) {
        const int g = slot + 148 * it;
        const int buf = it & 1;
        gg_cur = gg_next;

        if (it + 1 < ngenes) {
            const int gn = slot + 148 * (it + 1);
            gg_next = genes_oi[gn];
            prefetch(gn, gg_next, buf ^ 1);
            asm volatile("cp.async.commit_group;\n");
            asm volatile("cp.async.wait_group 1;\n");
        } else {
            asm volatile("cp.async.wait_group 0;\n");
        }
        __syncthreads();     // buffers ready; also orders prev-gene hsm reads

        const uint32_t btBase = smem_u + OFF_BT0 + buf * SZ_BTBUF;
        const float* hts = (const float*)(smem_raw + OFF_HTS0 + buf * 512);
        const float* rw_sh = (const float*)(smem_raw + OFF_RW0 + buf * 256);
        const unsigned short* recs_sh =
            (const unsigned short*)(smem_raw + OFF_RECS0 + buf * 640);
        const int* cnt_sh = (const int*)(smem_raw + OFF_CNT0 + buf * 512);
        const int ncuts = min(*(const int*)(smem_raw + OFF_HIST0 + buf * 16), CAP);
        const int t = g * 2 + half;

        // --- MMA phase (ldmatrix fragment loads) ---
        float c[4][4][4];
        #pragma unroll
        for (int mi = 0; mi < 4; mi++)
            #pragma unroll
            for (int nj = 0; nj < 4; nj++)
                #pragma unroll
                for (int q = 0; q < 4; q++) c[mi][nj][q] = 0.0f;

        #pragma unroll
        for (int ki = 0; ki < 4; ki++) {
            uint32_t a[4][4];
            #pragma unroll
            for (int mi = 0; mi < 4; mi++)
                ldsm_x4(a[mi][0], a[mi][1], a[mi][2], a[mi][3],
                        aAddr + mi * (16 * LDA * 2) + ki * 32);
            uint32_t b[4][2];
            #pragma unroll
            for (int p = 0; p < 2; p++)
                ldsm_x4(b[2 * p][0], b[2 * p][1], b[2 * p + 1][0], b[2 * p + 1][1],
                        btBase + bOff + p * (16 * LDB * 2) + ki * 32);
            #pragma unroll
            for (int mi = 0; mi < 4; mi++)
                #pragma unroll
                for (int nj = 0; nj < 4; nj++) {
                    asm volatile(
                        "mma.sync.aligned.m16n8k16.row.col.f32.bf16.bf16.f32 "
                        "{%0,%1,%2,%3}, {%4,%5,%6,%7}, {%8,%9}, {%0,%1,%2,%3};"
                        : "+f"(c[mi][nj][0]), "+f"(c[mi][nj][1]),
                          "+f"(c[mi][nj][2]), "+f"(c[mi][nj][3])
                        : "r"(a[mi][0]), "r"(a[mi][1]), "r"(a[mi][2]), "r"(a[mi][3]),
                          "r"(b[nj][0]), "r"(b[nj][1]));
                }
        }

        // --- Merged epilogue (base-2): h' = c + hts*log2e; store h'; ex2 sums ---
        float2 ht[4];
        #pragma unroll
        for (int nj = 0; nj < 4; nj++) {
            float2 v = *(const float2*)(hts + nw * 32 + 8 * nj + 2 * tig);
            ht[nj] = make_float2(v.x * LOG2E, v.y * LOG2E);
        }

        #pragma unroll
        for (int mi = 0; mi < 4; mi++) {
            const int r0 = mw * 64 + 16 * mi + grp;
            float s0 = 0.0f, s1 = 0.0f;
            #pragma unroll
            for (int nj = 0; nj < 4; nj++) {
                const int col = nw * 32 + 8 * nj + 2 * tig;
                const float h00 = c[mi][nj][0] + ht[nj].x;
                const float h01 = c[mi][nj][1] + ht[nj].y;
                const float h10 = c[mi][nj][2] + ht[nj].x;
                const float h11 = c[mi][nj][3] + ht[nj].y;
                *(__nv_bfloat162*)(hsm + r0 * LDH + col) =
                    __float22bfloat162_rn(make_float2(h00, h01));
                *(__nv_bfloat162*)(hsm + (r0 + 8) * LDH + col) =
                    __float22bfloat162_rn(make_float2(h10, h11));
                s0 += ex2f(h00) + ex2f(h01);
                s1 += ex2f(h10) + ex2f(h11);
            }
            s0 += __shfl_xor_sync(0xffffffffu, s0, 1);
            s0 += __shfl_xor_sync(0xffffffffu, s0, 2);
            s1 += __shfl_xor_sync(0xffffffffu, s1, 1);
            s1 += __shfl_xor_sync(0xffffffffu, s1, 2);
            if (tig == 0) {
                lsebuf[r0 * 4 + nw] = s0;
                lsebuf[(r0 + 8) * 4 + nw] = s1;
            }
        }
        __syncthreads();

        // --- lg2 finalize (tids 0..127) || Poisson (tids 128..255) ---
        if (tid < 128) {
            float tt = lsebuf[tid * 4 + 0] + lsebuf[tid * 4 + 1]
                     + lsebuf[tid * 4 + 2] + lsebuf[tid * 4 + 3];
            lse_sh[tid] = lg2f(tt);
        } else {
            const int r = tid - 128;
            const uint2* ar = (const uint2*)(Asm + r * LDA);
            float rd = 0.0f;
            #pragma unroll
            for (int j = 0; j < 16; j++) {
                uint2 w = ar[j];
                float2 v0 = __bfloat1622float2(*reinterpret_cast<const __nv_bfloat162*>(&w.x));
                float2 v1 = __bfloat1622float2(*reinterpret_cast<const __nv_bfloat162*>(&w.y));
                rd += v0.x * rw_sh[4 * j + 0] + v0.y * rw_sh[4 * j + 1]
                    + v1.x * rw_sh[4 * j + 2] + v1.y * rw_sh[4 * j + 3];
            }
            const int b_glob = half * 128 + r;
            const float rate = rho_bias[gg_cur] * __expf(rd)
                             * (float)libsize[cells_oi[b_glob]];
            const int cnt = cnt_sh[r];
            g_counts[g * NB + b_glob] = 0;          // restore invariant
            float lg = 0.0f;
            for (int k = 2; k <= cnt; k++) lg += __logf((float)k);
            acc += (float)cnt * __logf(rate) - rate - lg;
        }
        __syncthreads();    // hsm + lse_sh ready for cut lookups

        // --- cut likelihood from smem recs: (h' - lse2) * ln2 ---
        {
            for (int j = tid; j < ncuts; j += 256) {
                const unsigned int rec = recs_sh[j];
                const int b_loc = rec >> 7;
                acc += (__bfloat162float(hsm[b_loc * LDH + (rec & 127)])
                        - lse_sh[b_loc]) * LN2;
            }
            if (tid == 0) {
                acc += (float)ncuts * LOG_NBINS;
                g_hist[t] = 0;                      // restore invariant
            }
        }
        // next iteration's top __syncthreads orders hsm/lse_sh reuse
    }

    // --- block reduce + global accumulate + ticketed finalization ---
    {
        __shared__ float sred[8];
        #pragma unroll
        for (int o = 16; o > 0; o >>= 1)
            acc += __shfl_xor_sync(0xffffffffu, acc, o);
        if (lane == 0) sred[warp] = acc;
        __syncthreads();
        if (tid == 0) {
            float tt = 0.0f;
            #pragma unroll
            for (int w = 0; w < 8; w++) tt += sred[w];
            atomicAdd(&g_acc, (double)tt);
            __threadfence();
            unsigned int v = atomicAdd(&g_done, 1u);
            if (v == gridDim.x - 1) {
                __threadfence();
                double a = *((volatile double*)&g_acc);
                out[0] = (float)(-a);
                g_acc = 0.0;
                g_done = 0u;
            }
        }
    }
}

extern "C" void kernel_launch(void* const* d_in, const int* in_sizes, int n_in,
                              void* d_out, int out_size) {
    const float* latent     = (const float*)d_in[0];
    const int*   genes_oi   = (const int*)d_in[1];
    const int*   cells_oi   = (const int*)d_in[2];
    const float* coords     = (const float*)d_in[3];
    const int*   cut_cxg    = (const int*)d_in[4];
    const int*   local_cxg  = (const int*)d_in[6];
    const float* logit_w    = (const float*)d_in[7];
    const float* rho_w      = (const float*)d_in[8];
    const float* rho_b      = (const float*)d_in[9];
    const int*   libsize    = (const int*)d_in[10];
    const float* spline_h   = (const float*)d_in[11];
    float* out = (float*)d_out;

    cudaFuncSetAttribute(gemm_kernel,
                         cudaFuncAttributeMaxDynamicSharedMemorySize, SMEM_TOTAL);

    prep_kernel<<<LAT_BLOCKS + WT_BLOCKS + CUT_BLOCKS, 256, PREP_SMEM>>>(
        local_cxg, cut_cxg, coords, latent, genes_oi, logit_w);
    gemm_kernel<<<NBLK, 256, SMEM_TOTAL>>>(genes_oi, spline_h, cells_oi,
                                           rho_w, rho_b, libsize, out);
}